// round 6
// baseline (speedup 1.0000x reference)
#include <cuda_runtime.h>
#include <cuda_bf16.h>

// Fused conv1(3->16)+GELU -> conv2(16->18) -> deformable bilinear sampling.
// R5: packed fma.rn.f32x2 in both conv stages (2 FMAs/instr), weights
// pre-paired into __constant__ by a prep kernel + D2D memcpyToSymbol.

#define TSX 32
#define TSY 16
#define HTX (TSX + 2)   // 34
#define HTY (TSY + 2)   // 18
#define HPITCH 34
#define ITX (TSX + 4)   // 36
#define ITY (TSY + 4)   // 20
#define HH 512
#define WW 512
#define HWS (HH * WW)

typedef unsigned long long ull;

// packed weights: c_pw1[t*8+q] = (w1[2q*27+t], w1[(2q+1)*27+t])
__constant__ float2 c_pw1[216];
// broadcast-packed conv2 weights: c_pw2[i] = (w2[i], w2[i])
__constant__ float2 c_pw2[2592];
__constant__ float  c_b1[16];
__constant__ float  c_b2[18];
__constant__ float  c_wt[9];

// staging for device-side packing (static, not an allocation)
__device__ float2 g_pw1[216];
__device__ float2 g_pw2[2592];

__global__ void pack_weights(const float* __restrict__ w1,
                             const float* __restrict__ w2) {
    int i = threadIdx.x;
    for (int t = i; t < 216; t += 256) {
        int tt = t >> 3, q = t & 7;
        g_pw1[t] = make_float2(w1[(2 * q) * 27 + tt], w1[(2 * q + 1) * 27 + tt]);
    }
    for (int t = i; t < 2592; t += 256) {
        float w = w2[t];
        g_pw2[t] = make_float2(w, w);
    }
}

__device__ __forceinline__ ull pk(float lo, float hi) {
    ull r; asm("mov.b64 %0,{%1,%2};" : "=l"(r) : "f"(lo), "f"(hi)); return r;
}
__device__ __forceinline__ void unpk(ull v, float& lo, float& hi) {
    asm("mov.b64 {%0,%1},%2;" : "=f"(lo), "=f"(hi) : "l"(v));
}
__device__ __forceinline__ void fma2(ull& d, ull a, ull b) {
    asm("fma.rn.f32x2 %0,%1,%2,%0;" : "+l"(d) : "l"(a), "l"(b));
}

__global__ __launch_bounds__(256, 4)
void fused_residual_advection(const float* __restrict__ pm25,
                              const float* __restrict__ wind,
                              const float* __restrict__ topo,
                              float* __restrict__ out) {
    __shared__ float s_in[3][ITY][ITX];      // 8640 B
    __shared__ float s_h[16][HTY][HPITCH];   // 39168 B

    const int tid = threadIdx.x;
    const int b   = blockIdx.z;
    const int ty0 = blockIdx.y * TSY;
    const int tx0 = blockIdx.x * TSX;

    // ---- load zero-padded input tile [wind0, wind1, topo] ----
    const float* windb = wind + (size_t)b * 2 * HWS;
    const float* topob = topo + (size_t)b * HWS;
    for (int i = tid; i < 3 * ITY * ITX; i += 256) {
        int c  = i / (ITY * ITX);
        int r  = i - c * (ITY * ITX);
        int iy = r / ITX, ix = r - iy * ITX;
        int gy = ty0 - 2 + iy, gx = tx0 - 2 + ix;
        float v = 0.f;
        if ((unsigned)gy < HH && (unsigned)gx < WW) {
            v = (c < 2) ? windb[c * HWS + gy * WW + gx] : topob[gy * WW + gx];
        }
        s_in[c][iy][ix] = v;
    }
    __syncthreads();

    // ---- stage 1: h = gelu(conv1) on 18x34 halo tile, 8 channel-pairs ----
    for (int p = tid; p < HTY * HTX; p += 256) {
        int hy = p / HTX, hx = p - hy * HTX;
        int gy = ty0 - 1 + hy, gx = tx0 - 1 + hx;
        if ((unsigned)gy >= HH || (unsigned)gx >= WW) {
            #pragma unroll
            for (int o = 0; o < 16; o++) s_h[o][hy][hx] = 0.f;
        } else {
            ull acc[8];
            #pragma unroll
            for (int q = 0; q < 8; q++) acc[q] = pk(c_b1[2 * q], c_b1[2 * q + 1]);
            #pragma unroll
            for (int c = 0; c < 3; c++)
                #pragma unroll
                for (int ky = 0; ky < 3; ky++)
                    #pragma unroll
                    for (int kx = 0; kx < 3; kx++) {
                        const int t = (c * 3 + ky) * 3 + kx;
                        float v = s_in[c][hy + ky][hx + kx];
                        ull v2 = pk(v, v);
                        #pragma unroll
                        for (int q = 0; q < 8; q++)
                            fma2(acc[q], v2, *(const ull*)&c_pw1[t * 8 + q]);
                    }
            #pragma unroll
            for (int q = 0; q < 8; q++) {
                float x0, x1; unpk(acc[q], x0, x1);
                s_h[2 * q][hy][hx]     = x0 * normcdff(x0);  // exact GELU
                s_h[2 * q + 1][hy][hx] = x1 * normcdff(x1);
            }
        }
    }
    __syncthreads();

    // ---- stage 2: 2 horizontal outputs/thread, packed accumulators ----
    const int py  = tid >> 4;
    const int px2 = (tid & 15) * 2;
    const int gy  = ty0 + py;
    const int gx0 = tx0 + px2;
    const float* pimg = pm25 + (size_t)b * HWS;

    float out0 = 0.f, out1 = 0.f;
    #pragma unroll 1
    for (int k = 0; k < 9; k++) {
        float wk = c_wt[k];
        if (wk == 0.f) continue;   // warp-uniform skip

        ull dyP = pk(c_b2[2 * k],     c_b2[2 * k]);
        ull dxP = pk(c_b2[2 * k + 1], c_b2[2 * k + 1]);
        const float2* w2y = c_pw2 + (2 * k) * 144;
        const float2* w2x = c_pw2 + (2 * k + 1) * 144;
        #pragma unroll
        for (int ky = 0; ky < 3; ky++) {
            #pragma unroll
            for (int ci = 0; ci < 16; ci++) {
                const float2 a = *(const float2*)&s_h[ci][py + ky][px2];
                const float2 c = *(const float2*)&s_h[ci][py + ky][px2 + 2];
                ull A  = pk(a.x, a.y);
                ull Bm = pk(a.y, c.x);
                ull C  = pk(c.x, c.y);
                const int wi = ci * 9 + ky * 3;
                fma2(dyP, A,  *(const ull*)&w2y[wi]);
                fma2(dyP, Bm, *(const ull*)&w2y[wi + 1]);
                fma2(dyP, C,  *(const ull*)&w2y[wi + 2]);
                fma2(dxP, A,  *(const ull*)&w2x[wi]);
                fma2(dxP, Bm, *(const ull*)&w2x[wi + 1]);
                fma2(dxP, C,  *(const ull*)&w2x[wi + 2]);
            }
        }
        float dy0, dy1, dx0, dx1;
        unpk(dyP, dy0, dy1);
        unpk(dxP, dx0, dx1);

        const float kyo = (float)(k / 3 - 1);
        const float kxo = (float)(k % 3 - 1);
        #pragma unroll
        for (int px = 0; px < 2; px++) {
            float dyv = px ? dy1 : dy0;
            float dxv = px ? dx1 : dx0;
            float py_ = (float)gy + kyo + dyv;
            float px_ = (float)(gx0 + px) + kxo + dxv;
            float y0f = floorf(py_), x0f = floorf(px_);
            float wy = py_ - y0f, wx = px_ - x0f;
            int y0 = (int)y0f, x0 = (int)x0f;
            int y1 = y0 + 1,   x1 = x0 + 1;
            bool vy0 = (unsigned)y0 < HH, vy1 = (unsigned)y1 < HH;
            bool vx0 = (unsigned)x0 < WW, vx1 = (unsigned)x1 < WW;
            int yc0 = min(max(y0, 0), HH - 1), yc1 = min(max(y1, 0), HH - 1);
            int xc0 = min(max(x0, 0), WW - 1), xc1 = min(max(x1, 0), WW - 1);
            const float* r0 = pimg + yc0 * WW;
            const float* r1 = pimg + yc1 * WW;
            float v00 = (vy0 && vx0) ? r0[xc0] : 0.f;
            float v01 = (vy0 && vx1) ? r0[xc1] : 0.f;
            float v10 = (vy1 && vx0) ? r1[xc0] : 0.f;
            float v11 = (vy1 && vx1) ? r1[xc1] : 0.f;
            float samp = (1.f - wy) * (1.f - wx) * v00
                       + (1.f - wy) * wx         * v01
                       + wy         * (1.f - wx) * v10
                       + wy         * wx         * v11;
            if (px) out1 = fmaf(samp, wk, out1);
            else    out0 = fmaf(samp, wk, out0);
        }
    }

    *(float2*)&out[(size_t)b * HWS + (size_t)gy * WW + gx0] = make_float2(out0, out1);
}

extern "C" void kernel_launch(void* const* d_in, const int* in_sizes, int n_in,
                              void* d_out, int out_size) {
    const float* pm25 = (const float*)d_in[0];
    const float* wind = (const float*)d_in[1];
    const float* topo = (const float*)d_in[2];

    // pack weights on device, then stage into constant memory (all D2D, capturable)
    pack_weights<<<1, 256>>>((const float*)d_in[3], (const float*)d_in[5]);

    void* pw1_addr = nullptr;
    void* pw2_addr = nullptr;
    cudaGetSymbolAddress(&pw1_addr, g_pw1);
    cudaGetSymbolAddress(&pw2_addr, g_pw2);
    cudaMemcpyToSymbolAsync(c_pw1, pw1_addr, 216  * sizeof(float2), 0, cudaMemcpyDeviceToDevice);
    cudaMemcpyToSymbolAsync(c_pw2, pw2_addr, 2592 * sizeof(float2), 0, cudaMemcpyDeviceToDevice);
    cudaMemcpyToSymbolAsync(c_b1, d_in[4], 16 * sizeof(float), 0, cudaMemcpyDeviceToDevice);
    cudaMemcpyToSymbolAsync(c_b2, d_in[6], 18 * sizeof(float), 0, cudaMemcpyDeviceToDevice);
    cudaMemcpyToSymbolAsync(c_wt, d_in[7], 9  * sizeof(float), 0, cudaMemcpyDeviceToDevice);

    float* out = (float*)d_out;
    int B = in_sizes[0] / (HH * WW);
    dim3 grid(WW / TSX, HH / TSY, B);
    fused_residual_advection<<<grid, 256>>>(pm25, wind, topo, out);
}

// round 7
// speedup vs baseline: 1.2371x; 1.2371x over previous
#include <cuda_runtime.h>
#include <cuda_bf16.h>

// Fused conv1(3->16)+exact GELU -> conv2(16->18) -> deformable bilinear
// sampling. R7: scalar FFMA (f32x2 proven throughput-neutral), stage-1
// 2-px/thread weight-load amortization, fast A&S-erf GELU.

#define TSX 32
#define TSY 16
#define HTX (TSX + 2)   // 34
#define HTY (TSY + 2)   // 18
#define HPITCH 34
#define ITX (TSX + 4)   // 36
#define ITY (TSY + 4)   // 20
#define HH 512
#define WW 512
#define HWS (HH * WW)

__constant__ float c_w1[432];    // (16,3,3,3)
__constant__ float c_b1[16];
__constant__ float c_w2[2592];   // (18,16,3,3)
__constant__ float c_b2[18];
__constant__ float c_wt[9];

// exact GELU via Abramowitz-Stegun 7.1.26 erf (|abs err| <= 1.5e-7)
__device__ __forceinline__ float gelu_fast(float x) {
    float z = 0.70710678118f * x;
    float a = fabsf(z);
    float t = __fdividef(1.0f, fmaf(0.3275911f, a, 1.0f));
    float p = fmaf(1.061405429f, t, -1.453152027f);
    p = fmaf(p, t, 1.421413741f);
    p = fmaf(p, t, -0.284496736f);
    p = fmaf(p, t, 0.254829592f);
    p = p * t;
    float e = __expf(-a * a);
    float erfa = fmaf(-p, e, 1.0f);          // erf(|z|)
    float erfz = copysignf(erfa, z);
    return x * (0.5f * (1.0f + erfz));       // x * Phi(x)
}

__global__ __launch_bounds__(256, 4)
void fused_residual_advection(const float* __restrict__ pm25,
                              const float* __restrict__ wind,
                              const float* __restrict__ topo,
                              float* __restrict__ out) {
    __shared__ float s_in[3][ITY][ITX];      // 8640 B
    __shared__ float s_h[16][HTY][HPITCH];   // 39168 B

    const int tid = threadIdx.x;
    const int b   = blockIdx.z;
    const int ty0 = blockIdx.y * TSY;
    const int tx0 = blockIdx.x * TSX;

    // ---- load zero-padded input tile [wind0, wind1, topo] ----
    const float* windb = wind + (size_t)b * 2 * HWS;
    const float* topob = topo + (size_t)b * HWS;
    for (int i = tid; i < 3 * ITY * ITX; i += 256) {
        int c  = i / (ITY * ITX);
        int r  = i - c * (ITY * ITX);
        int iy = r / ITX, ix = r - iy * ITX;
        int gy = ty0 - 2 + iy, gx = tx0 - 2 + ix;
        float v = 0.f;
        if ((unsigned)gy < HH && (unsigned)gx < WW) {
            v = (c < 2) ? windb[c * HWS + gy * WW + gx] : topob[gy * WW + gx];
        }
        s_in[c][iy][ix] = v;
    }
    __syncthreads();

    // ---- stage 1: h = gelu(conv1) on 18x34 tile, 2 horizontal px/thread ----
    // 17 column-pairs x 18 rows = 306 work items over 256 threads.
    for (int p = tid; p < 18 * 17; p += 256) {
        const int hy  = p / 17;
        const int hx0 = (p - hy * 17) * 2;
        const int gy  = ty0 - 1 + hy;
        const int gx0 = tx0 - 1 + hx0;
        const bool rowv = (unsigned)gy < HH;
        const bool v0 = rowv && (unsigned)gx0 < WW;
        const bool v1 = rowv && (unsigned)(gx0 + 1) < WW;

        float in_reg[3][3][4];
        #pragma unroll
        for (int c = 0; c < 3; c++)
            #pragma unroll
            for (int ky = 0; ky < 3; ky++)
                #pragma unroll
                for (int j = 0; j < 4; j++)
                    in_reg[c][ky][j] = s_in[c][hy + ky][hx0 + j];

        #pragma unroll
        for (int o = 0; o < 16; o++) {
            float a0 = c_b1[o], a1 = a0;
            #pragma unroll
            for (int c = 0; c < 3; c++)
                #pragma unroll
                for (int ky = 0; ky < 3; ky++)
                    #pragma unroll
                    for (int kx = 0; kx < 3; kx++) {
                        const float w = c_w1[o * 27 + (c * 3 + ky) * 3 + kx];
                        a0 = fmaf(in_reg[c][ky][kx],     w, a0);
                        a1 = fmaf(in_reg[c][ky][kx + 1], w, a1);
                    }
            s_h[o][hy][hx0]     = v0 ? gelu_fast(a0) : 0.f;
            s_h[o][hy][hx0 + 1] = v1 ? gelu_fast(a1) : 0.f;
        }
    }
    __syncthreads();

    // ---- stage 2: 2 horizontal outputs per thread (R4 structure) ----
    const int py  = tid >> 4;
    const int px2 = (tid & 15) * 2;
    const int gy  = ty0 + py;
    const int gx0 = tx0 + px2;
    const float* pimg = pm25 + (size_t)b * HWS;

    float out0 = 0.f, out1 = 0.f;
    #pragma unroll 1
    for (int k = 0; k < 9; k++) {
        float wk = c_wt[k];
        if (wk == 0.f) continue;   // warp-uniform skip

        float dy0 = c_b2[2 * k],     dy1 = dy0;
        float dx0 = c_b2[2 * k + 1], dx1 = dx0;
        const int wbase_y = (2 * k) * 144;
        const int wbase_x = (2 * k + 1) * 144;
        #pragma unroll
        for (int ky = 0; ky < 3; ky++) {
            #pragma unroll
            for (int ci = 0; ci < 16; ci++) {
                const float2 a = *(const float2*)&s_h[ci][py + ky][px2];
                const float2 c = *(const float2*)&s_h[ci][py + ky][px2 + 2];
                const int wi = ci * 9 + ky * 3;
                float wy0 = c_w2[wbase_y + wi + 0];
                float wy1 = c_w2[wbase_y + wi + 1];
                float wy2 = c_w2[wbase_y + wi + 2];
                float wx0 = c_w2[wbase_x + wi + 0];
                float wx1 = c_w2[wbase_x + wi + 1];
                float wx2 = c_w2[wbase_x + wi + 2];
                dy0 = fmaf(a.x, wy0, dy0); dy0 = fmaf(a.y, wy1, dy0); dy0 = fmaf(c.x, wy2, dy0);
                dy1 = fmaf(a.y, wy0, dy1); dy1 = fmaf(c.x, wy1, dy1); dy1 = fmaf(c.y, wy2, dy1);
                dx0 = fmaf(a.x, wx0, dx0); dx0 = fmaf(a.y, wx1, dx0); dx0 = fmaf(c.x, wx2, dx0);
                dx1 = fmaf(a.y, wx0, dx1); dx1 = fmaf(c.x, wx1, dx1); dx1 = fmaf(c.y, wx2, dx1);
            }
        }

        const float kyo = (float)(k / 3 - 1);
        const float kxo = (float)(k % 3 - 1);
        #pragma unroll
        for (int px = 0; px < 2; px++) {
            float dyv = px ? dy1 : dy0;
            float dxv = px ? dx1 : dx0;
            float py_ = (float)gy + kyo + dyv;
            float px_ = (float)(gx0 + px) + kxo + dxv;
            float y0f = floorf(py_), x0f = floorf(px_);
            float wy = py_ - y0f, wx = px_ - x0f;
            int y0 = (int)y0f, x0 = (int)x0f;
            int y1 = y0 + 1,   x1 = x0 + 1;
            bool vy0 = (unsigned)y0 < HH, vy1 = (unsigned)y1 < HH;
            bool vx0 = (unsigned)x0 < WW, vx1 = (unsigned)x1 < WW;
            int yc0 = min(max(y0, 0), HH - 1), yc1 = min(max(y1, 0), HH - 1);
            int xc0 = min(max(x0, 0), WW - 1), xc1 = min(max(x1, 0), WW - 1);
            const float* r0 = pimg + yc0 * WW;
            const float* r1 = pimg + yc1 * WW;
            float v00 = (vy0 && vx0) ? r0[xc0] : 0.f;
            float v01 = (vy0 && vx1) ? r0[xc1] : 0.f;
            float v10 = (vy1 && vx0) ? r1[xc0] : 0.f;
            float v11 = (vy1 && vx1) ? r1[xc1] : 0.f;
            float samp = (1.f - wy) * (1.f - wx) * v00
                       + (1.f - wy) * wx         * v01
                       + wy         * (1.f - wx) * v10
                       + wy         * wx         * v11;
            if (px) out1 = fmaf(samp, wk, out1);
            else    out0 = fmaf(samp, wk, out0);
        }
    }

    *(float2*)&out[(size_t)b * HWS + (size_t)gy * WW + gx0] = make_float2(out0, out1);
}

extern "C" void kernel_launch(void* const* d_in, const int* in_sizes, int n_in,
                              void* d_out, int out_size) {
    const float* pm25 = (const float*)d_in[0];
    const float* wind = (const float*)d_in[1];
    const float* topo = (const float*)d_in[2];

    cudaMemcpyToSymbolAsync(c_w1, d_in[3], 432  * sizeof(float), 0, cudaMemcpyDeviceToDevice);
    cudaMemcpyToSymbolAsync(c_b1, d_in[4], 16   * sizeof(float), 0, cudaMemcpyDeviceToDevice);
    cudaMemcpyToSymbolAsync(c_w2, d_in[5], 2592 * sizeof(float), 0, cudaMemcpyDeviceToDevice);
    cudaMemcpyToSymbolAsync(c_b2, d_in[6], 18   * sizeof(float), 0, cudaMemcpyDeviceToDevice);
    cudaMemcpyToSymbolAsync(c_wt, d_in[7], 9    * sizeof(float), 0, cudaMemcpyDeviceToDevice);

    float* out = (float*)d_out;
    int B = in_sizes[0] / (HH * WW);
    dim3 grid(WW / TSX, HH / TSY, B);
    fused_residual_advection<<<grid, 256>>>(pm25, wind, topo, out);
}